// round 3
// baseline (speedup 1.0000x reference)
#include <cuda_runtime.h>
#include <cuda_bf16.h>
#include <math.h>

// feat_rgb: [B=4, C=256, IH=128, IW=512] fp32
// out:      [4, 256, BEV_H=128, BEV_W=512] fp32
#define BEV_H 128
#define BEV_W 512
#define IH    128
#define IW    512
#define NB    4
#define NC    256
#define PLANE (IH * IW)
#define CHUNK 64
#define NCH   (NC / CHUNK)
#define JV    4                    // j-vectorization width (STG.128)

#define TWO_PI_F   6.2831853071795864769f
#define PI_F       3.1415926535897932385f
#define HALF_PI_F  1.5707963267948966192f

__device__ __forceinline__ float mod2pi(float x) {
    float m = fmodf(x, TWO_PI_F);
    if (m < 0.0f) m += TWO_PI_F;
    return m;
}

__global__ void __launch_bounds__(256)
bev_project_kernel(const float* __restrict__ feat,
                   const float* __restrict__ rot,
                   const float* __restrict__ shift_u,
                   const float* __restrict__ shift_v,
                   const float* __restrict__ mpp,
                   float* __restrict__ out)
{
    int t = blockIdx.x * blockDim.x + threadIdx.x;
    // t layout: [b][cc][i][j4], j4 fastest. 4*4*128*128 = 262144 threads.
    int j4 = t & (BEV_W / JV - 1);          // 0..127
    int i  = (t >> 7) & (BEV_H - 1);        // 0..127
    int cc = (t >> 14) & (NCH - 1);         // 0..3
    int b  = (t >> 16);                     // 0..3

    const float r  = rot[b];
    const float su = shift_u[b];
    const float sv = shift_v[b];
    const float m  = mpp[0];

    const float center_v = (float)BEV_H * 0.5f - 0.5f + sv;
    const float center_u = (float)BEV_W * 0.5f - 0.5f + su;
    const float dy = (float)i - center_v;
    const float rterm = r * TWO_PI_F;

    // --- per-pixel coordinates, weights, corner indices (JV pixels) ---
    float w00[JV], w01[JV], w10[JV], w11[JV];
    int   i00[JV], i01[JV], i10[JV], i11[JV];

    #pragma unroll
    for (int q = 0; q < JV; ++q) {
        int j = j4 * JV + q;
        float dx = (float)j - center_u;
        float radius = sqrtf(dy * dy + dx * dx);

        float theta = atan2f(dy, dx);
        theta = mod2pi(-HALF_PI_F + mod2pi(theta));
        theta = mod2pi(theta + rterm);
        float u = theta / TWO_PI_F * (float)IW;

        float dist = radius * m;
        float phi  = atan2f(dist, -2.0f);
        float v    = phi / PI_F * (float)IH;

        float fx = floorf(u);
        float fy = floorf(v);
        float x0 = fminf(fmaxf(fx,        0.0f), (float)(IW - 1));
        float x1 = fminf(fmaxf(fx + 1.0f, 0.0f), (float)(IW - 1));
        float y0 = fminf(fmaxf(fy,        0.0f), (float)(IH - 1));
        float y1 = fminf(fmaxf(fy + 1.0f, 0.0f), (float)(IH - 1));

        w00[q] = (x1 - u) * (y1 - v);
        w01[q] = (u - x0) * (y1 - v);
        w10[q] = (x1 - u) * (v - y0);
        w11[q] = (u - x0) * (v - y0);

        int ix0 = (int)x0, ix1 = (int)x1, iy0 = (int)y0, iy1 = (int)y1;
        i00[q] = iy0 * IW + ix0;
        i01[q] = iy0 * IW + ix1;
        i10[q] = iy1 * IW + ix0;
        i11[q] = iy1 * IW + ix1;
    }

    // --- channel loop: 16 gathers + 1 STG.128 per channel ---
    int c0 = cc * CHUNK;
    const float* __restrict__ p = feat + (size_t)(b * NC + c0) * PLANE;
    float4* __restrict__ o = (float4*)(out
        + (size_t)((b * NC + c0) * BEV_H + i) * BEV_W + j4 * JV);

    #pragma unroll 2
    for (int c = 0; c < CHUNK; ++c) {
        float a00[JV], a01[JV], a10[JV], a11[JV];
        #pragma unroll
        for (int q = 0; q < JV; ++q) {
            a00[q] = __ldg(p + i00[q]);
            a01[q] = __ldg(p + i01[q]);
            a10[q] = __ldg(p + i10[q]);
            a11[q] = __ldg(p + i11[q]);
        }
        float4 val;
        val.x = a00[0] * w00[0] + a01[0] * w01[0] + a10[0] * w10[0] + a11[0] * w11[0];
        val.y = a00[1] * w00[1] + a01[1] * w01[1] + a10[1] * w10[1] + a11[1] * w11[1];
        val.z = a00[2] * w00[2] + a01[2] * w01[2] + a10[2] * w10[2] + a11[2] * w11[2];
        val.w = a00[3] * w00[3] + a01[3] * w01[3] + a10[3] * w10[3] + a11[3] * w11[3];
        __stcs(o, val);
        p += PLANE;
        o += (size_t)(BEV_H * BEV_W) / JV;
    }
}

extern "C" void kernel_launch(void* const* d_in, const int* in_sizes, int n_in,
                              void* d_out, int out_size)
{
    const float* feat    = (const float*)d_in[0];
    const float* rot     = (const float*)d_in[1];
    const float* shift_u = (const float*)d_in[2];
    const float* shift_v = (const float*)d_in[3];
    const float* mpp     = (const float*)d_in[4];
    float* out = (float*)d_out;

    int total = NB * NCH * BEV_H * (BEV_W / JV);   // 262144 threads
    int threads = 256;
    int blocks = total / threads;                  // 1024
    bev_project_kernel<<<blocks, threads>>>(feat, rot, shift_u, shift_v, mpp, out);
}

// round 4
// speedup vs baseline: 1.3321x; 1.3321x over previous
#include <cuda_runtime.h>
#include <cuda_bf16.h>
#include <math.h>

// feat_rgb: [B=4, C=256, IH=128, IW=512] fp32
// out:      [4, 256, BEV_H=128, BEV_W=512] fp32
#define BEV_H 128
#define BEV_W 512
#define IH    128
#define IW    512
#define NB    4
#define NC    256
#define PLANE (IH * IW)
#define CHUNK 64                   // channels per thread
#define NCH   (NC / CHUNK)
#define UB    8                    // channel batch (loads in flight: 4*UB)

#define TWO_PI_F   6.2831853071795864769f
#define PI_F       3.1415926535897932385f
#define HALF_PI_F  1.5707963267948966192f

__device__ __forceinline__ float mod2pi(float x) {
    float m = fmodf(x, TWO_PI_F);
    if (m < 0.0f) m += TWO_PI_F;
    return m;
}

__global__ void __launch_bounds__(256)
bev_project_kernel(const float* __restrict__ feat,
                   const float* __restrict__ rot,
                   const float* __restrict__ shift_u,
                   const float* __restrict__ shift_v,
                   const float* __restrict__ mpp,
                   float* __restrict__ out)
{
    int t = blockIdx.x * blockDim.x + threadIdx.x;
    // layout: [b][cc][i][j], j fastest -> warp = 32 consecutive j (critical)
    int j  = t & (BEV_W - 1);
    int i  = (t >> 9) & (BEV_H - 1);
    int cc = (t >> 16) & (NCH - 1);
    int b  = t >> 18;

    const float r  = rot[b];
    const float su = shift_u[b];
    const float sv = shift_v[b];
    const float m  = mpp[0];

    // --- coordinates (bit-identical to R1) ---
    float center_v = (float)BEV_H * 0.5f - 0.5f + sv;
    float center_u = (float)BEV_W * 0.5f - 0.5f + su;
    float dy = (float)i - center_v;
    float dx = (float)j - center_u;
    float radius = sqrtf(dy * dy + dx * dx);

    float theta = atan2f(dy, dx);
    theta = mod2pi(-HALF_PI_F + mod2pi(theta));
    theta = mod2pi(theta + r * TWO_PI_F);
    float u = theta / TWO_PI_F * (float)IW;

    float dist = radius * m;
    float phi  = atan2f(dist, -2.0f);
    float v    = phi / PI_F * (float)IH;

    float fx = floorf(u);
    float fy = floorf(v);
    float x0 = fminf(fmaxf(fx,        0.0f), (float)(IW - 1));
    float x1 = fminf(fmaxf(fx + 1.0f, 0.0f), (float)(IW - 1));
    float y0 = fminf(fmaxf(fy,        0.0f), (float)(IH - 1));
    float y1 = fminf(fmaxf(fy + 1.0f, 0.0f), (float)(IH - 1));

    float w_nw = (x1 - u) * (y1 - v);
    float w_ne = (u - x0) * (y1 - v);
    float w_sw = (x1 - u) * (v - y0);
    float w_se = (u - x0) * (v - y0);

    int ix0 = (int)x0, ix1 = (int)x1, iy0 = (int)y0, iy1 = (int)y1;
    int i00 = iy0 * IW + ix0;
    int i01 = iy0 * IW + ix1;
    int i10 = iy1 * IW + ix0;
    int i11 = iy1 * IW + ix1;

    int c0 = cc * CHUNK;
    const float* __restrict__ p = feat + (size_t)(b * NC + c0) * PLANE;
    float* __restrict__ o = out + (size_t)((b * NC + c0) * BEV_H + i) * BEV_W + j;

    // --- channel loop: batch UB channels, issue all 4*UB gathers first ---
    #pragma unroll 1
    for (int c = 0; c < CHUNK; c += UB) {
        float a00[UB], a01[UB], a10[UB], a11[UB];
        const float* pp = p;
        #pragma unroll
        for (int q = 0; q < UB; ++q) {
            a00[q] = __ldg(pp + i00);
            a01[q] = __ldg(pp + i01);
            a10[q] = __ldg(pp + i10);
            a11[q] = __ldg(pp + i11);
            pp += PLANE;
        }
        float* oo = o;
        #pragma unroll
        for (int q = 0; q < UB; ++q) {
            float val = a00[q] * w_nw + a01[q] * w_ne
                      + a10[q] * w_sw + a11[q] * w_se;
            __stcs(oo, val);
            oo += (size_t)BEV_H * BEV_W;
        }
        p += (size_t)UB * PLANE;
        o += (size_t)UB * BEV_H * BEV_W;
    }
}

extern "C" void kernel_launch(void* const* d_in, const int* in_sizes, int n_in,
                              void* d_out, int out_size)
{
    const float* feat    = (const float*)d_in[0];
    const float* rot     = (const float*)d_in[1];
    const float* shift_u = (const float*)d_in[2];
    const float* shift_v = (const float*)d_in[3];
    const float* mpp     = (const float*)d_in[4];
    float* out = (float*)d_out;

    int total = NB * NCH * BEV_H * BEV_W;   // 1,048,576 threads
    int threads = 256;
    int blocks = total / threads;           // 4096
    bev_project_kernel<<<blocks, threads>>>(feat, rot, shift_u, shift_v, mpp, out);
}